// round 2
// baseline (speedup 1.0000x reference)
#include <cuda_runtime.h>
#include <math.h>

#define B_   16
#define L_   18
#define SQ_  256
#define H_   2560
#define R_   256
#define D_   2048
#define C_   32
#define TOPK_ 16

// Scratch (no allocations allowed -> device globals)
__device__ float g_qvec[B_ * L_ * R_];          // 1.18 MB
__device__ float g_sims[B_ * D_ * L_];          // 2.36 MB  [b][d][l]

// ---------------------------------------------------------------------------
// Kernel A: per-(b,l) GEMM  C[s,r] = sum_h q_hs[b,l,s,h] * w_q[l,r,h]
// then max over s, written to g_qvec[b,l,r]. Block = 256 thr, tile 128x128x16,
// 8x8 register micro-tile, double-buffered smem, m-loop (2 tiles) inside block.
// ---------------------------------------------------------------------------
__global__ void __launch_bounds__(256, 2)
qproj_kernel(const float* __restrict__ q_hs, const float* __restrict__ w_q) {
    const int nt = blockIdx.x;   // r-tile: 0..1
    const int l  = blockIdx.y;
    const int b  = blockIdx.z;

    const float* Abase = q_hs + ((size_t)(b * L_ + l)) * SQ_ * H_;
    const float* Wbase = w_q + (size_t)l * R_ * H_ + (size_t)nt * 128 * H_;

    __shared__ float As[2][16][132];   // [buf][k][m], padded
    __shared__ float Bs[2][16][132];   // [buf][k][n]
    __shared__ float red[16][128];

    const int tid = threadIdx.x;
    const int tx  = tid & 15;     // n group
    const int ty  = tid >> 4;     // m group

    // load mapping: 512 float4 per tile, 2 per thread
    const int lr0 = tid >> 2;     // rows 0..63
    const int lc  = tid & 3;      // col-quad 0..3
    const int lr1 = lr0 + 64;

    float cmax[8];
#pragma unroll
    for (int j = 0; j < 8; j++) cmax[j] = -INFINITY;

    float4 ra0, ra1, rb0, rb1;

#define LOAD_TILE(Aptr, K0)                                                    \
    do {                                                                       \
        ra0 = *(const float4*)((Aptr) + (size_t)lr0 * H_ + (K0) + lc * 4);     \
        ra1 = *(const float4*)((Aptr) + (size_t)lr1 * H_ + (K0) + lc * 4);     \
        rb0 = *(const float4*)(Wbase + (size_t)lr0 * H_ + (K0) + lc * 4);      \
        rb1 = *(const float4*)(Wbase + (size_t)lr1 * H_ + (K0) + lc * 4);      \
    } while (0)

#define STORE_TILE(BUF)                                                        \
    do {                                                                       \
        As[BUF][lc * 4 + 0][lr0] = ra0.x; As[BUF][lc * 4 + 1][lr0] = ra0.y;    \
        As[BUF][lc * 4 + 2][lr0] = ra0.z; As[BUF][lc * 4 + 3][lr0] = ra0.w;    \
        As[BUF][lc * 4 + 0][lr1] = ra1.x; As[BUF][lc * 4 + 1][lr1] = ra1.y;    \
        As[BUF][lc * 4 + 2][lr1] = ra1.z; As[BUF][lc * 4 + 3][lr1] = ra1.w;    \
        Bs[BUF][lc * 4 + 0][lr0] = rb0.x; Bs[BUF][lc * 4 + 1][lr0] = rb0.y;    \
        Bs[BUF][lc * 4 + 2][lr0] = rb0.z; Bs[BUF][lc * 4 + 3][lr0] = rb0.w;    \
        Bs[BUF][lc * 4 + 0][lr1] = rb1.x; Bs[BUF][lc * 4 + 1][lr1] = rb1.y;    \
        Bs[BUF][lc * 4 + 2][lr1] = rb1.z; Bs[BUF][lc * 4 + 3][lr1] = rb1.w;    \
    } while (0)

    for (int mt = 0; mt < 2; mt++) {
        const float* A = Abase + (size_t)mt * 128 * H_;

        float acc[8][8];
#pragma unroll
        for (int i = 0; i < 8; i++)
#pragma unroll
            for (int j = 0; j < 8; j++) acc[i][j] = 0.0f;

        LOAD_TILE(A, 0);
        STORE_TILE(0);
        __syncthreads();

        const int NST = H_ / 16;   // 160
        for (int s = 0; s < NST; s++) {
            const int buf = s & 1;
            if (s + 1 < NST) LOAD_TILE(A, (s + 1) * 16);

#pragma unroll
            for (int k = 0; k < 16; k++) {
                float4 a0 = *(const float4*)&As[buf][k][ty * 8];
                float4 a1 = *(const float4*)&As[buf][k][ty * 8 + 4];
                float4 b0 = *(const float4*)&Bs[buf][k][tx * 8];
                float4 b1 = *(const float4*)&Bs[buf][k][tx * 8 + 4];
                float av[8] = {a0.x, a0.y, a0.z, a0.w, a1.x, a1.y, a1.z, a1.w};
                float bv[8] = {b0.x, b0.y, b0.z, b0.w, b1.x, b1.y, b1.z, b1.w};
#pragma unroll
                for (int i = 0; i < 8; i++)
#pragma unroll
                    for (int j = 0; j < 8; j++)
                        acc[i][j] = fmaf(av[i], bv[j], acc[i][j]);
            }

            if (s + 1 < NST) {
                STORE_TILE(buf ^ 1);
                __syncthreads();
            }
        }

        // fold this m-tile into the per-column running max
#pragma unroll
        for (int i = 0; i < 8; i++)
#pragma unroll
            for (int j = 0; j < 8; j++) cmax[j] = fmaxf(cmax[j], acc[i][j]);
    }

    // reduce max across the 16 m-thread-groups
#pragma unroll
    for (int j = 0; j < 8; j++) red[ty][tx * 8 + j] = cmax[j];
    __syncthreads();
    if (tid < 128) {
        float m = red[0][tid];
#pragma unroll
        for (int i = 1; i < 16; i++) m = fmaxf(m, red[i][tid]);
        g_qvec[((size_t)(b * L_ + l)) * R_ + nt * 128 + tid] = m;
    }
#undef LOAD_TILE
#undef STORE_TILE
}

// ---------------------------------------------------------------------------
// Kernel A2: L2-normalize each of the 288 rows of g_qvec (len 256) in place.
// ---------------------------------------------------------------------------
__global__ void qnorm_kernel() {
    const int row = blockIdx.x;
    const int tid = threadIdx.x;   // 256
    float v = g_qvec[(size_t)row * R_ + tid];
    __shared__ float sm[256];
    sm[tid] = v * v;
    __syncthreads();
    for (int s = 128; s > 0; s >>= 1) {
        if (tid < s) sm[tid] += sm[tid + s];
        __syncthreads();
    }
    float inv = 1.0f / fmaxf(sqrtf(sm[0]), 1e-12f);
    g_qvec[(size_t)row * R_ + tid] = v * inv;
}

// ---------------------------------------------------------------------------
// Kernel B: per-(d,l) block. Normalize each of the 32 chunk keys on the fly,
// dot with all 16 normalized query vectors, max over chunks -> g_sims[b,d,l].
// Warp-per-chunk, 4 chunks per warp.
// ---------------------------------------------------------------------------
__global__ void __launch_bounds__(256)
docsim_kernel(const float* __restrict__ doc_keys) {
    const int d = blockIdx.x;
    const int l = blockIdx.y;
    const int tid = threadIdx.x;

    __shared__ float4 qs[B_ * 64];   // [b][r/4], 16 KB
    for (int i = tid; i < B_ * 64; i += 256) {
        int b = i >> 6, j = i & 63;
        qs[i] = *(const float4*)&g_qvec[((size_t)(b * L_ + l)) * R_ + j * 4];
    }
    __syncthreads();

    const int w = tid >> 5, lane = tid & 31;
    float bmax[16];
#pragma unroll
    for (int b = 0; b < 16; b++) bmax[b] = -INFINITY;

    const float* kb = doc_keys + ((size_t)(d * L_ + l)) * C_ * R_;

    for (int ci = 0; ci < 4; ci++) {
        const int c = w * 4 + ci;
        const float4* kp = (const float4*)(kb + (size_t)c * R_);
        float4 k0 = kp[lane];
        float4 k1 = kp[lane + 32];

        float n2 = k0.x * k0.x + k0.y * k0.y + k0.z * k0.z + k0.w * k0.w +
                   k1.x * k1.x + k1.y * k1.y + k1.z * k1.z + k1.w * k1.w;
#pragma unroll
        for (int off = 16; off > 0; off >>= 1)
            n2 += __shfl_xor_sync(0xffffffffu, n2, off);
        const float inv = 1.0f / fmaxf(sqrtf(n2), 1e-12f);

#pragma unroll
        for (int b = 0; b < 16; b++) {
            float4 q0 = qs[b * 64 + lane];
            float4 q1 = qs[b * 64 + 32 + lane];
            float p = k0.x * q0.x + k0.y * q0.y + k0.z * q0.z + k0.w * q0.w +
                      k1.x * q1.x + k1.y * q1.y + k1.z * q1.z + k1.w * q1.w;
#pragma unroll
            for (int off = 16; off > 0; off >>= 1)
                p += __shfl_xor_sync(0xffffffffu, p, off);
            bmax[b] = fmaxf(bmax[b], p * inv);
        }
    }

    __shared__ float red[8][16];
    if (lane == 0) {
#pragma unroll
        for (int b = 0; b < 16; b++) red[w][b] = bmax[b];
    }
    __syncthreads();
    if (tid < 16) {
        float m = red[0][tid];
#pragma unroll
        for (int i = 1; i < 8; i++) m = fmaxf(m, red[i][tid]);
        g_sims[((size_t)(tid * D_ + d)) * L_ + l] = m;
    }
}

// ---------------------------------------------------------------------------
// Kernel C: per-b block: scores[d] = mean_l sims[b,d,l]; exact top-16
// (descending, ties -> lower index first), write scores then indices (as f32).
// ---------------------------------------------------------------------------
__global__ void topk_kernel(float* __restrict__ out, int out_size) {
    const int b = blockIdx.x;
    const int tid = threadIdx.x;   // 256
    __shared__ float sv[D_];
    for (int i = tid; i < D_; i += 256) {
        const float* p = &g_sims[((size_t)(b * D_ + i)) * L_];
        float ssum = 0.0f;
#pragma unroll
        for (int l = 0; l < L_; l++) ssum += p[l];
        sv[i] = ssum / (float)L_;
    }
    __syncthreads();

    __shared__ float rv[256];
    __shared__ int ri[256];
    for (int k = 0; k < TOPK_; k++) {
        float best = -INFINITY;
        int bi = 0x7fffffff;
        for (int i = tid; i < D_; i += 256) {
            float v = sv[i];
            if (v > best || (v == best && i < bi)) { best = v; bi = i; }
        }
        rv[tid] = best; ri[tid] = bi;
        __syncthreads();
        for (int s = 128; s > 0; s >>= 1) {
            if (tid < s) {
                float v2 = rv[tid + s]; int i2 = ri[tid + s];
                if (v2 > rv[tid] || (v2 == rv[tid] && i2 < ri[tid])) {
                    rv[tid] = v2; ri[tid] = i2;
                }
            }
            __syncthreads();
        }
        if (tid == 0) {
            out[b * TOPK_ + k] = rv[0];
            if (out_size >= 2 * B_ * TOPK_)
                out[B_ * TOPK_ + b * TOPK_ + k] = (float)ri[0];
            sv[ri[0]] = -INFINITY;
        }
        __syncthreads();
    }
}

// ---------------------------------------------------------------------------
extern "C" void kernel_launch(void* const* d_in, const int* in_sizes, int n_in,
                              void* d_out, int out_size) {
    const float* q_hs     = (const float*)d_in[0];
    const float* w_q      = (const float*)d_in[1];
    const float* doc_keys = (const float*)d_in[2];
    // d_in[3] = top_k scalar (constant 16, baked in)
    (void)in_sizes; (void)n_in;

    dim3 gA(2, L_, B_);
    qproj_kernel<<<gA, 256>>>(q_hs, w_q);

    qnorm_kernel<<<B_ * L_, 256>>>();

    dim3 gB(D_, L_);
    docsim_kernel<<<gB, 256>>>(doc_keys);

    topk_kernel<<<B_, 256>>>((float*)d_out, out_size);
}

// round 5
// speedup vs baseline: 2.2711x; 2.2711x over previous
#include <cuda_runtime.h>
#include <cuda_bf16.h>
#include <math.h>
#include <stdint.h>

#define B_   16
#define L_   18
#define SQ_  256
#define H_   2560
#define R_   256
#define D_   2048
#define C_   32
#define TOPK_ 16

#define NQ_ (B_*L_*SQ_*H_)
#define NW_ (L_*R_*H_)

__device__ float g_qpart[2 * B_ * L_ * R_];     // [pair][mt][256 cols]
__device__ float g_qvec[B_ * L_ * R_];
__device__ float g_sims[B_ * D_ * L_];
__device__ __nv_bfloat16 g_ahi[NQ_];
__device__ __nv_bfloat16 g_alo[NQ_];
__device__ __nv_bfloat16 g_whi[NW_];
__device__ __nv_bfloat16 g_wlo[NW_];

// ---------------- helpers ----------------
__device__ __forceinline__ uint32_t smem_u32(const void* p) {
    uint32_t a;
    asm("{ .reg .u64 t; cvta.to.shared.u64 t, %1; cvt.u32.u64 %0, t; }" : "=r"(a) : "l"(p));
    return a;
}
#define CP16(d, s) asm volatile("cp.async.cg.shared.global [%0], [%1], 16;" :: "r"(d), "l"(s))
#define CP_COMMIT() asm volatile("cp.async.commit_group;" ::: "memory")
#define CP_WAIT2() asm volatile("cp.async.wait_group 2;" ::: "memory")
#define CP_WAIT1() asm volatile("cp.async.wait_group 1;" ::: "memory")
#define CP_WAIT0() asm volatile("cp.async.wait_group 0;" ::: "memory")

__device__ __forceinline__ void ldm_x4(uint32_t a, uint32_t* r) {
    asm volatile("ldmatrix.sync.aligned.m8n8.x4.shared.b16 {%0,%1,%2,%3}, [%4];"
        : "=r"(r[0]), "=r"(r[1]), "=r"(r[2]), "=r"(r[3]) : "r"(a));
}
__device__ __forceinline__ void mma16816(float* c, const uint32_t* a, const uint32_t* b) {
    asm volatile("mma.sync.aligned.m16n8k16.row.col.f32.bf16.bf16.f32 "
        "{%0,%1,%2,%3}, {%4,%5,%6,%7}, {%8,%9}, {%0,%1,%2,%3};"
        : "+f"(c[0]), "+f"(c[1]), "+f"(c[2]), "+f"(c[3])
        : "r"(a[0]), "r"(a[1]), "r"(a[2]), "r"(a[3]), "r"(b[0]), "r"(b[1]));
}

// stage layout: rows stored with 80-byte stride (odd*16 -> ldmatrix conflict-free)
#define ROWB 80
#define OAH 0
#define OAL 10240
#define OBH 20480
#define OBL 30720
#define STG_ 40960
#define NSTAGE 4
#define QP_DSM (NSTAGE * STG_)

// ---------------- split fp32 -> bf16 hi/lo ----------------
__device__ __forceinline__ void split4(const float* __restrict__ src,
                                       __nv_bfloat16* __restrict__ hi,
                                       __nv_bfloat16* __restrict__ lo, int i) {
    float4 f = reinterpret_cast<const float4*>(src)[i];
    float v[4] = {f.x, f.y, f.z, f.w};
    __nv_bfloat16 h[4], l[4];
#pragma unroll
    for (int j = 0; j < 4; j++) {
        h[j] = __float2bfloat16_rn(v[j]);
        l[j] = __float2bfloat16_rn(v[j] - __bfloat162float(h[j]));
    }
    __nv_bfloat162 a{h[0], h[1]}, b{h[2], h[3]}, c{l[0], l[1]}, d{l[2], l[3]};
    reinterpret_cast<__nv_bfloat162*>(hi)[i*2+0] = a;
    reinterpret_cast<__nv_bfloat162*>(hi)[i*2+1] = b;
    reinterpret_cast<__nv_bfloat162*>(lo)[i*2+0] = c;
    reinterpret_cast<__nv_bfloat162*>(lo)[i*2+1] = d;
}
__global__ void split_q_kernel(const float* __restrict__ s) {
    int i = blockIdx.x * 256 + threadIdx.x;
    if (i < NQ_/4) split4(s, g_ahi, g_alo, i);
}
__global__ void split_w_kernel(const float* __restrict__ s) {
    int i = blockIdx.x * 256 + threadIdx.x;
    if (i < NW_/4) split4(s, g_whi, g_wlo, i);
}

// ---------------- bf16x3 mma.sync GEMM + fused max-pool ----------------
// block: (mt,nt) in blockIdx.x (0..3), pair=b*L+l in blockIdx.y
// tile 128(M) x 128(N), 8 warps (2x4), warp tile 64x32, k-chunk 32, 4 stages.
__global__ void __launch_bounds__(256, 1) qproj_mma() {
    extern __shared__ char dsm[];
    __shared__ float sred[2][128];

    const uint32_t sb = smem_u32(dsm);
    const int mt = blockIdx.x & 1;
    const int nt = blockIdx.x >> 1;
    const int pair = blockIdx.y;
    const int l = pair % L_;

    const int tid = threadIdx.x;
    const int wid = tid >> 5;
    const int lane = tid & 31;
    const int warp_m = wid >> 2;    // 0..1
    const int warp_n = wid & 3;     // 0..3

    const __nv_bfloat16* Ah = g_ahi + ((size_t)pair * SQ_ + mt * 128) * H_;
    const __nv_bfloat16* Al = g_alo + ((size_t)pair * SQ_ + mt * 128) * H_;
    const __nv_bfloat16* Wh = g_whi + ((size_t)l * R_ + nt * 128) * H_;
    const __nv_bfloat16* Wl = g_wlo + ((size_t)l * R_ + nt * 128) * H_;

    // loader mapping: idx in [0,512): row=idx>>2 (0..127), c=idx&3 (16B chunk)
    const int r0 = tid >> 2, c0 = tid & 3;
    const int r1 = r0 + 64;

#define REFILL(t)                                                              \
    do {                                                                       \
        const int _k0 = (t) * 32;                                              \
        const uint32_t _s = sb + ((t) & 3) * STG_;                             \
        {                                                                      \
            const uint32_t dd = _s + r0 * ROWB + c0 * 16;                      \
            const size_t off = (size_t)r0 * H_ + _k0 + c0 * 8;                 \
            CP16(dd + OAH, (const void*)(Ah + off));                          \
            CP16(dd + OAL, (const void*)(Al + off));                          \
            CP16(dd + OBH, (const void*)(Wh + off));                          \
            CP16(dd + OBL, (const void*)(Wl + off));                          \
        }                                                                      \
        {                                                                      \
            const uint32_t dd = _s + r1 * ROWB + c0 * 16;                      \
            const size_t off = (size_t)r1 * H_ + _k0 + c0 * 8;                 \
            CP16(dd + OAH, (const void*)(Ah + off));                          \
            CP16(dd + OAL, (const void*)(Al + off));                          \
            CP16(dd + OBH, (const void*)(Wh + off));                          \
            CP16(dd + OBL, (const void*)(Wl + off));                          \
        }                                                                      \
        CP_COMMIT();                                                           \
    } while (0)

    float acc[4][4][4];
#pragma unroll
    for (int m = 0; m < 4; m++)
#pragma unroll
        for (int n = 0; n < 4; n++)
#pragma unroll
            for (int r = 0; r < 4; r++) acc[m][n][r] = 0.0f;

    REFILL(0); REFILL(1); REFILL(2);

    // ldmatrix address components
    const uint32_t aRow = (uint32_t)(warp_m * 64 + (lane & 15)) * ROWB;
    const uint32_t aKsel = ((lane >> 4) & 1) * 16;
    const uint32_t bRow = (uint32_t)(warp_n * 32 + ((lane >> 4) & 1) * 8 + (lane & 7)) * ROWB;
    const uint32_t bKsel = ((lane >> 3) & 1) * 16;

    const int NCH = H_ / 32;   // 80
    for (int t = 0; t < NCH; t++) {
        if (t + 3 < NCH) CP_WAIT2();
        else if (t + 2 < NCH) CP_WAIT1();
        else CP_WAIT0();
        __syncthreads();
        if (t + 3 < NCH) REFILL(t + 3);

        const uint32_t s = sb + (t & 3) * STG_;
#pragma unroll
        for (int ks = 0; ks < 2; ks++) {
            const uint32_t ka = ks * 32 + aKsel;
            const uint32_t kb = ks * 32 + bKsel;
            uint32_t ah[4][4], al[4][4], bh[2][4], bl[2][4];
#pragma unroll
            for (int m = 0; m < 4; m++) {
                ldm_x4(s + OAH + aRow + m * (16 * ROWB) + ka, ah[m]);
                ldm_x4(s + OAL + aRow + m * (16 * ROWB) + ka, al[m]);
            }
#pragma unroll
            for (int p = 0; p < 2; p++) {
                ldm_x4(s + OBH + bRow + p * (16 * ROWB) + kb, bh[p]);
                ldm_x4(s + OBL + bRow + p * (16 * ROWB) + kb, bl[p]);
            }
#pragma unroll
            for (int m = 0; m < 4; m++)
#pragma unroll
                for (int n = 0; n < 4; n++) {
                    const uint32_t* ph = &bh[n >> 1][(n & 1) * 2];
                    const uint32_t* pl = &bl[n >> 1][(n & 1) * 2];
                    mma16816(acc[m][n], ah[m], ph);
                    mma16816(acc[m][n], ah[m], pl);
                    mma16816(acc[m][n], al[m], ph);
                }
        }
    }

    // epilogue: max over M, fold to sred, then g_qpart
#pragma unroll
    for (int n = 0; n < 4; n++) {
        float m0 = -INFINITY, m1 = -INFINITY;
#pragma unroll
        for (int m = 0; m < 4; m++) {
            m0 = fmaxf(m0, fmaxf(acc[m][n][0], acc[m][n][2]));
            m1 = fmaxf(m1, fmaxf(acc[m][n][1], acc[m][n][3]));
        }
#pragma unroll
        for (int off = 4; off < 32; off <<= 1) {
            m0 = fmaxf(m0, __shfl_xor_sync(0xffffffffu, m0, off));
            m1 = fmaxf(m1, __shfl_xor_sync(0xffffffffu, m1, off));
        }
        if (lane < 4) {
            sred[warp_m][warp_n * 32 + n * 8 + lane * 2 + 0] = m0;
            sred[warp_m][warp_n * 32 + n * 8 + lane * 2 + 1] = m1;
        }
    }
    __syncthreads();
    if (tid < 128) {
        g_qpart[((size_t)pair * 2 + mt) * R_ + nt * 128 + tid] =
            fmaxf(sred[0][tid], sred[1][tid]);
    }
#undef REFILL
}

// ---------------- normalize ----------------
__global__ void qnorm_kernel() {
    const int row = blockIdx.x;
    const int tid = threadIdx.x;
    float v = fmaxf(g_qpart[((size_t)row * 2 + 0) * R_ + tid],
                    g_qpart[((size_t)row * 2 + 1) * R_ + tid]);
    __shared__ float sm[256];
    sm[tid] = v * v;
    __syncthreads();
    for (int s = 128; s > 0; s >>= 1) {
        if (tid < s) sm[tid] += sm[tid + s];
        __syncthreads();
    }
    float inv = 1.0f / fmaxf(sqrtf(sm[0]), 1e-12f);
    g_qvec[(size_t)row * R_ + tid] = v * inv;
}

// ---------------- doc sims ----------------
__global__ void __launch_bounds__(256)
docsim_kernel(const float* __restrict__ doc_keys) {
    const int d = blockIdx.x;
    const int l = blockIdx.y;
    const int tid = threadIdx.x;

    __shared__ float4 qs[B_ * 64];
    for (int i = tid; i < B_ * 64; i += 256) {
        int b = i >> 6, j = i & 63;
        qs[i] = *(const float4*)&g_qvec[((size_t)(b * L_ + l)) * R_ + j * 4];
    }
    __syncthreads();

    const int w = tid >> 5, lane = tid & 31;
    float bmax[16];
#pragma unroll
    for (int b = 0; b < 16; b++) bmax[b] = -INFINITY;

    const float* kb = doc_keys + ((size_t)(d * L_ + l)) * C_ * R_;
    for (int ci = 0; ci < 4; ci++) {
        const int c = w * 4 + ci;
        const float4* kp = (const float4*)(kb + (size_t)c * R_);
        float4 k0 = kp[lane], k1 = kp[lane + 32];
        float n2 = k0.x*k0.x + k0.y*k0.y + k0.z*k0.z + k0.w*k0.w +
                   k1.x*k1.x + k1.y*k1.y + k1.z*k1.z + k1.w*k1.w;
#pragma unroll
        for (int off = 16; off > 0; off >>= 1) n2 += __shfl_xor_sync(0xffffffffu, n2, off);
        const float inv = 1.0f / fmaxf(sqrtf(n2), 1e-12f);
#pragma unroll
        for (int b = 0; b < 16; b++) {
            float4 q0 = qs[b * 64 + lane], q1 = qs[b * 64 + 32 + lane];
            float p = k0.x*q0.x + k0.y*q0.y + k0.z*q0.z + k0.w*q0.w +
                      k1.x*q1.x + k1.y*q1.y + k1.z*q1.z + k1.w*q1.w;
#pragma unroll
            for (int off = 16; off > 0; off >>= 1) p += __shfl_xor_sync(0xffffffffu, p, off);
            bmax[b] = fmaxf(bmax[b], p * inv);
        }
    }
    __shared__ float red[8][16];
    if (lane == 0) {
#pragma unroll
        for (int b = 0; b < 16; b++) red[w][b] = bmax[b];
    }
    __syncthreads();
    if (tid < 16) {
        float m = red[0][tid];
#pragma unroll
        for (int i = 1; i < 8; i++) m = fmaxf(m, red[i][tid]);
        g_sims[((size_t)(tid * D_ + d)) * L_ + l] = m;
    }
}

// ---------------- top-k ----------------
__global__ void topk_kernel(float* __restrict__ out, int out_size) {
    const int b = blockIdx.x;
    const int tid = threadIdx.x;
    __shared__ float sv[D_];
    for (int i = tid; i < D_; i += 256) {
        const float* p = &g_sims[((size_t)(b * D_ + i)) * L_];
        float ssum = 0.0f;
#pragma unroll
        for (int l = 0; l < L_; l++) ssum += p[l];
        sv[i] = ssum / (float)L_;
    }
    __syncthreads();
    __shared__ float rv[256];
    __shared__ int ri[256];
    for (int k = 0; k < TOPK_; k++) {
        float best = -INFINITY; int bi = 0x7fffffff;
        for (int i = tid; i < D_; i += 256) {
            float v = sv[i];
            if (v > best || (v == best && i < bi)) { best = v; bi = i; }
        }
        rv[tid] = best; ri[tid] = bi;
        __syncthreads();
        for (int s = 128; s > 0; s >>= 1) {
            if (tid < s) {
                float v2 = rv[tid + s]; int i2 = ri[tid + s];
                if (v2 > rv[tid] || (v2 == rv[tid] && i2 < ri[tid])) { rv[tid] = v2; ri[tid] = i2; }
            }
            __syncthreads();
        }
        if (tid == 0) {
            out[b * TOPK_ + k] = rv[0];
            if (out_size >= 2 * B_ * TOPK_) out[B_ * TOPK_ + b * TOPK_ + k] = (float)ri[0];
            sv[ri[0]] = -INFINITY;
        }
        __syncthreads();
    }
}

// ---------------------------------------------------------------------------
extern "C" void kernel_launch(void* const* d_in, const int* in_sizes, int n_in,
                              void* d_out, int out_size) {
    const float* q_hs     = (const float*)d_in[0];
    const float* w_q      = (const float*)d_in[1];
    const float* doc_keys = (const float*)d_in[2];
    (void)in_sizes; (void)n_in;

    cudaFuncSetAttribute(qproj_mma, cudaFuncAttributeMaxDynamicSharedMemorySize, QP_DSM);

    split_q_kernel<<<NQ_ / 4 / 256, 256>>>(q_hs);
    split_w_kernel<<<NW_ / 4 / 256, 256>>>(w_q);
    dim3 gA(4, B_ * L_);
    qproj_mma<<<gA, 256, QP_DSM>>>();
    qnorm_kernel<<<B_ * L_, 256>>>();
    dim3 gB(D_, L_);
    docsim_kernel<<<gB, 256>>>(doc_keys);
    topk_kernel<<<B_, 256>>>((float*)d_out, out_size);
}

// round 6
// speedup vs baseline: 2.4422x; 1.0753x over previous
#include <cuda_runtime.h>
#include <cuda_bf16.h>
#include <math.h>
#include <stdint.h>

#define B_   16
#define L_   18
#define SQ_  256
#define H_   2560
#define R_   256
#define D_   2048
#define C_   32
#define TOPK_ 16

#define NQ_ (B_*L_*SQ_*H_)
#define NW_ (L_*R_*H_)

__device__ float g_qpart[2 * B_ * L_ * R_];     // [pair][mt][256 cols]
__device__ float g_qvec[B_ * L_ * R_];
__device__ float g_sims[B_ * D_ * L_];
__device__ __nv_bfloat16 g_ahi[NQ_];
__device__ __nv_bfloat16 g_alo[NQ_];
__device__ __nv_bfloat16 g_whi[NW_];
__device__ __nv_bfloat16 g_wlo[NW_];

// ---------------- helpers ----------------
__device__ __forceinline__ uint32_t smem_u32(const void* p) {
    uint32_t a;
    asm("{ .reg .u64 t; cvta.to.shared.u64 t, %1; cvt.u32.u64 %0, t; }" : "=r"(a) : "l"(p));
    return a;
}
#define CP16(d, s) asm volatile("cp.async.cg.shared.global [%0], [%1], 16;" :: "r"(d), "l"(s))
#define CP_COMMIT() asm volatile("cp.async.commit_group;" ::: "memory")
#define CP_WAIT1() asm volatile("cp.async.wait_group 1;" ::: "memory")
#define CP_WAIT0() asm volatile("cp.async.wait_group 0;" ::: "memory")

__device__ __forceinline__ void ldm_x4(uint32_t a, uint32_t* r) {
    asm volatile("ldmatrix.sync.aligned.m8n8.x4.shared.b16 {%0,%1,%2,%3}, [%4];"
        : "=r"(r[0]), "=r"(r[1]), "=r"(r[2]), "=r"(r[3]) : "r"(a));
}
__device__ __forceinline__ void mma16816(float* c, const uint32_t* a, const uint32_t* b) {
    asm volatile("mma.sync.aligned.m16n8k16.row.col.f32.bf16.bf16.f32 "
        "{%0,%1,%2,%3}, {%4,%5,%6,%7}, {%8,%9}, {%0,%1,%2,%3};"
        : "+f"(c[0]), "+f"(c[1]), "+f"(c[2]), "+f"(c[3])
        : "r"(a[0]), "r"(a[1]), "r"(a[2]), "r"(a[3]), "r"(b[0]), "r"(b[1]));
}

// stage layout: rows stored with 80-byte stride (odd*16 -> ldmatrix conflict-free)
#define ROWB 80
#define OAH 0
#define OAL 10240
#define OBH 20480
#define OBL 30720
#define STG_ 40960
#define NSTAGE 2
#define QP_DSM (NSTAGE * STG_)

// ---------------- split fp32 -> bf16 hi/lo ----------------
__device__ __forceinline__ void split4(const float* __restrict__ src,
                                       __nv_bfloat16* __restrict__ hi,
                                       __nv_bfloat16* __restrict__ lo, int i) {
    float4 f = reinterpret_cast<const float4*>(src)[i];
    float v[4] = {f.x, f.y, f.z, f.w};
    __nv_bfloat16 h[4], l[4];
#pragma unroll
    for (int j = 0; j < 4; j++) {
        h[j] = __float2bfloat16_rn(v[j]);
        l[j] = __float2bfloat16_rn(v[j] - __bfloat162float(h[j]));
    }
    __nv_bfloat162 a{h[0], h[1]}, b{h[2], h[3]}, c{l[0], l[1]}, d{l[2], l[3]};
    reinterpret_cast<__nv_bfloat162*>(hi)[i*2+0] = a;
    reinterpret_cast<__nv_bfloat162*>(hi)[i*2+1] = b;
    reinterpret_cast<__nv_bfloat162*>(lo)[i*2+0] = c;
    reinterpret_cast<__nv_bfloat162*>(lo)[i*2+1] = d;
}
__global__ void split_q_kernel(const float* __restrict__ s) {
    int i = blockIdx.x * 256 + threadIdx.x;
    if (i < NQ_/4) split4(s, g_ahi, g_alo, i);
}
__global__ void split_w_kernel(const float* __restrict__ s) {
    int i = blockIdx.x * 256 + threadIdx.x;
    if (i < NW_/4) split4(s, g_whi, g_wlo, i);
}

// ---------------- bf16x3 mma.sync GEMM + fused max-pool ----------------
// block: (mt,nt) in blockIdx.x (0..3), pair=b*L+l in blockIdx.y
// tile 128(M) x 128(N), 8 warps (2x4), warp tile 64x32, k-chunk 32,
// 2 stages (80KB smem) -> 2 CTAs/SM for latency hiding.
__global__ void __launch_bounds__(256, 2) qproj_mma() {
    extern __shared__ char dsm[];
    __shared__ float sred[2][128];

    const uint32_t sb = smem_u32(dsm);
    const int mt = blockIdx.x & 1;
    const int nt = blockIdx.x >> 1;
    const int pair = blockIdx.y;
    const int l = pair % L_;

    const int tid = threadIdx.x;
    const int wid = tid >> 5;
    const int lane = tid & 31;
    const int warp_m = wid >> 2;    // 0..1
    const int warp_n = wid & 3;     // 0..3

    const __nv_bfloat16* Ah = g_ahi + ((size_t)pair * SQ_ + mt * 128) * H_;
    const __nv_bfloat16* Al = g_alo + ((size_t)pair * SQ_ + mt * 128) * H_;
    const __nv_bfloat16* Wh = g_whi + ((size_t)l * R_ + nt * 128) * H_;
    const __nv_bfloat16* Wl = g_wlo + ((size_t)l * R_ + nt * 128) * H_;

    // loader mapping: idx in [0,512): row=idx>>2 (0..127), c=idx&3 (16B chunk)
    const int r0 = tid >> 2, c0 = tid & 3;
    const int r1 = r0 + 64;

#define REFILL(t)                                                              \
    do {                                                                       \
        const int _k0 = (t) * 32;                                              \
        const uint32_t _s = sb + ((t) & 1) * STG_;                             \
        {                                                                      \
            const uint32_t dd = _s + r0 * ROWB + c0 * 16;                      \
            const size_t off = (size_t)r0 * H_ + _k0 + c0 * 8;                 \
            CP16(dd + OAH, (const void*)(Ah + off));                          \
            CP16(dd + OAL, (const void*)(Al + off));                          \
            CP16(dd + OBH, (const void*)(Wh + off));                          \
            CP16(dd + OBL, (const void*)(Wl + off));                          \
        }                                                                      \
        {                                                                      \
            const uint32_t dd = _s + r1 * ROWB + c0 * 16;                      \
            const size_t off = (size_t)r1 * H_ + _k0 + c0 * 8;                 \
            CP16(dd + OAH, (const void*)(Ah + off));                          \
            CP16(dd + OAL, (const void*)(Al + off));                          \
            CP16(dd + OBH, (const void*)(Wh + off));                          \
            CP16(dd + OBL, (const void*)(Wl + off));                          \
        }                                                                      \
        CP_COMMIT();                                                           \
    } while (0)

    float acc[4][4][4];
#pragma unroll
    for (int m = 0; m < 4; m++)
#pragma unroll
        for (int n = 0; n < 4; n++)
#pragma unroll
            for (int r = 0; r < 4; r++) acc[m][n][r] = 0.0f;

    REFILL(0); REFILL(1);

    // ldmatrix address components
    const uint32_t aRow = (uint32_t)(warp_m * 64 + (lane & 15)) * ROWB;
    const uint32_t aKsel = ((lane >> 4) & 1) * 16;
    const uint32_t bRow = (uint32_t)(warp_n * 32 + ((lane >> 4) & 1) * 8 + (lane & 7)) * ROWB;
    const uint32_t bKsel = ((lane >> 3) & 1) * 16;

    const int NCH = H_ / 32;   // 80
    for (int t = 0; t < NCH; t++) {
        if (t + 1 < NCH) CP_WAIT1(); else CP_WAIT0();
        __syncthreads();

        const uint32_t s = sb + (t & 1) * STG_;
#pragma unroll
        for (int ks = 0; ks < 2; ks++) {
            const uint32_t ka = ks * 32 + aKsel;
            const uint32_t kb = ks * 32 + bKsel;
            uint32_t ah[4][4], al[4][4], bh[2][4], bl[2][4];
#pragma unroll
            for (int m = 0; m < 4; m++) {
                ldm_x4(s + OAH + aRow + m * (16 * ROWB) + ka, ah[m]);
                ldm_x4(s + OAL + aRow + m * (16 * ROWB) + ka, al[m]);
            }
#pragma unroll
            for (int p = 0; p < 2; p++) {
                ldm_x4(s + OBH + bRow + p * (16 * ROWB) + kb, bh[p]);
                ldm_x4(s + OBL + bRow + p * (16 * ROWB) + kb, bl[p]);
            }
#pragma unroll
            for (int m = 0; m < 4; m++)
#pragma unroll
                for (int n = 0; n < 4; n++) {
                    const uint32_t* ph = &bh[n >> 1][(n & 1) * 2];
                    const uint32_t* pl = &bl[n >> 1][(n & 1) * 2];
                    mma16816(acc[m][n], ah[m], ph);
                    mma16816(acc[m][n], ah[m], pl);
                    mma16816(acc[m][n], al[m], ph);
                }
        }
        __syncthreads();
        if (t + 2 < NCH) REFILL(t + 2);
    }

    // epilogue: max over M, fold to sred, then g_qpart
#pragma unroll
    for (int n = 0; n < 4; n++) {
        float m0 = -INFINITY, m1 = -INFINITY;
#pragma unroll
        for (int m = 0; m < 4; m++) {
            m0 = fmaxf(m0, fmaxf(acc[m][n][0], acc[m][n][2]));
            m1 = fmaxf(m1, fmaxf(acc[m][n][1], acc[m][n][3]));
        }
#pragma unroll
        for (int off = 4; off < 32; off <<= 1) {
            m0 = fmaxf(m0, __shfl_xor_sync(0xffffffffu, m0, off));
            m1 = fmaxf(m1, __shfl_xor_sync(0xffffffffu, m1, off));
        }
        if (lane < 4) {
            sred[warp_m][warp_n * 32 + n * 8 + lane * 2 + 0] = m0;
            sred[warp_m][warp_n * 32 + n * 8 + lane * 2 + 1] = m1;
        }
    }
    __syncthreads();
    if (tid < 128) {
        g_qpart[((size_t)pair * 2 + mt) * R_ + nt * 128 + tid] =
            fmaxf(sred[0][tid], sred[1][tid]);
    }
#undef REFILL
}

// ---------------- normalize ----------------
__global__ void qnorm_kernel() {
    const int row = blockIdx.x;
    const int tid = threadIdx.x;
    float v = fmaxf(g_qpart[((size_t)row * 2 + 0) * R_ + tid],
                    g_qpart[((size_t)row * 2 + 1) * R_ + tid]);
    __shared__ float sm[256];
    sm[tid] = v * v;
    __syncthreads();
    for (int s = 128; s > 0; s >>= 1) {
        if (tid < s) sm[tid] += sm[tid + s];
        __syncthreads();
    }
    float inv = 1.0f / fmaxf(sqrtf(sm[0]), 1e-12f);
    g_qvec[(size_t)row * R_ + tid] = v * inv;
}

// ---------------- doc sims ----------------
__global__ void __launch_bounds__(256)
docsim_kernel(const float* __restrict__ doc_keys) {
    const int d = blockIdx.x;
    const int l = blockIdx.y;
    const int tid = threadIdx.x;

    __shared__ float4 qs[B_ * 64];
    for (int i = tid; i < B_ * 64; i += 256) {
        int b = i >> 6, j = i & 63;
        qs[i] = *(const float4*)&g_qvec[((size_t)(b * L_ + l)) * R_ + j * 4];
    }
    __syncthreads();

    const int w = tid >> 5, lane = tid & 31;
    float bmax[16];
#pragma unroll
    for (int b = 0; b < 16; b++) bmax[b] = -INFINITY;

    const float* kb = doc_keys + ((size_t)(d * L_ + l)) * C_ * R_;
    for (int ci = 0; ci < 4; ci++) {
        const int c = w * 4 + ci;
        const float4* kp = (const float4*)(kb + (size_t)c * R_);
        float4 k0 = kp[lane], k1 = kp[lane + 32];
        float n2 = k0.x*k0.x + k0.y*k0.y + k0.z*k0.z + k0.w*k0.w +
                   k1.x*k1.x + k1.y*k1.y + k1.z*k1.z + k1.w*k1.w;
#pragma unroll
        for (int off = 16; off > 0; off >>= 1) n2 += __shfl_xor_sync(0xffffffffu, n2, off);
        const float inv = 1.0f / fmaxf(sqrtf(n2), 1e-12f);
#pragma unroll
        for (int b = 0; b < 16; b++) {
            float4 q0 = qs[b * 64 + lane], q1 = qs[b * 64 + 32 + lane];
            float p = k0.x*q0.x + k0.y*q0.y + k0.z*q0.z + k0.w*q0.w +
                      k1.x*q1.x + k1.y*q1.y + k1.z*q1.z + k1.w*q1.w;
#pragma unroll
            for (int off = 16; off > 0; off >>= 1) p += __shfl_xor_sync(0xffffffffu, p, off);
            bmax[b] = fmaxf(bmax[b], p * inv);
        }
    }
    __shared__ float red[8][16];
    if (lane == 0) {
#pragma unroll
        for (int b = 0; b < 16; b++) red[w][b] = bmax[b];
    }
    __syncthreads();
    if (tid < 16) {
        float m = red[0][tid];
#pragma unroll
        for (int i = 1; i < 8; i++) m = fmaxf(m, red[i][tid]);
        g_sims[((size_t)(tid * D_ + d)) * L_ + l] = m;
    }
}

// ---------------- top-k ----------------
__global__ void topk_kernel(float* __restrict__ out, int out_size) {
    const int b = blockIdx.x;
    const int tid = threadIdx.x;
    __shared__ float sv[D_];
    for (int i = tid; i < D_; i += 256) {
        const float* p = &g_sims[((size_t)(b * D_ + i)) * L_];
        float ssum = 0.0f;
#pragma unroll
        for (int l = 0; l < L_; l++) ssum += p[l];
        sv[i] = ssum / (float)L_;
    }
    __syncthreads();
    __shared__ float rv[256];
    __shared__ int ri[256];
    for (int k = 0; k < TOPK_; k++) {
        float best = -INFINITY; int bi = 0x7fffffff;
        for (int i = tid; i < D_; i += 256) {
            float v = sv[i];
            if (v > best || (v == best && i < bi)) { best = v; bi = i; }
        }
        rv[tid] = best; ri[tid] = bi;
        __syncthreads();
        for (int s = 128; s > 0; s >>= 1) {
            if (tid < s) {
                float v2 = rv[tid + s]; int i2 = ri[tid + s];
                if (v2 > rv[tid] || (v2 == rv[tid] && i2 < ri[tid])) { rv[tid] = v2; ri[tid] = i2; }
            }
            __syncthreads();
        }
        if (tid == 0) {
            out[b * TOPK_ + k] = rv[0];
            if (out_size >= 2 * B_ * TOPK_) out[B_ * TOPK_ + b * TOPK_ + k] = (float)ri[0];
            sv[ri[0]] = -INFINITY;
        }
        __syncthreads();
    }
}

// ---------------------------------------------------------------------------
extern "C" void kernel_launch(void* const* d_in, const int* in_sizes, int n_in,
                              void* d_out, int out_size) {
    const float* q_hs     = (const float*)d_in[0];
    const float* w_q      = (const float*)d_in[1];
    const float* doc_keys = (const float*)d_in[2];
    (void)in_sizes; (void)n_in;

    cudaFuncSetAttribute(qproj_mma, cudaFuncAttributeMaxDynamicSharedMemorySize, QP_DSM);

    split_q_kernel<<<NQ_ / 4 / 256, 256>>>(q_hs);
    split_w_kernel<<<NW_ / 4 / 256, 256>>>(w_q);
    dim3 gA(4, B_ * L_);
    qproj_mma<<<gA, 256, QP_DSM>>>();
    qnorm_kernel<<<B_ * L_, 256>>>();
    dim3 gB(D_, L_);
    docsim_kernel<<<gB, 256>>>(doc_keys);
    topk_kernel<<<B_, 256>>>((float*)d_out, out_size);
}

// round 7
// speedup vs baseline: 2.4730x; 1.0126x over previous
#include <cuda_runtime.h>
#include <cuda_bf16.h>
#include <math.h>
#include <stdint.h>

#define B_   16
#define L_   18
#define SQ_  256
#define H_   2560
#define R_   256
#define D_   2048
#define C_   32
#define TOPK_ 16

#define NQ_ (B_*L_*SQ_*H_)
#define NW_ (L_*R_*H_)

__device__ float g_qpart[2 * B_ * L_ * R_];     // [pair][mt][256 cols]
__device__ float g_qvec[B_ * L_ * R_];
__device__ float g_sims[B_ * D_ * L_];
__device__ __nv_bfloat16 g_ahi[NQ_];
__device__ __nv_bfloat16 g_alo[NQ_];
__device__ __nv_bfloat16 g_whi[NW_];
__device__ __nv_bfloat16 g_wlo[NW_];

// ---------------- helpers ----------------
__device__ __forceinline__ uint32_t smem_u32(const void* p) {
    uint32_t a;
    asm("{ .reg .u64 t; cvta.to.shared.u64 t, %1; cvt.u32.u64 %0, t; }" : "=r"(a) : "l"(p));
    return a;
}
#define CP16(d, s) asm volatile("cp.async.cg.shared.global [%0], [%1], 16;" :: "r"(d), "l"(s))
#define CP_COMMIT() asm volatile("cp.async.commit_group;" ::: "memory")
#define CP_WAIT1() asm volatile("cp.async.wait_group 1;" ::: "memory")
#define CP_WAIT0() asm volatile("cp.async.wait_group 0;" ::: "memory")

__device__ __forceinline__ void ldm_x4(uint32_t a, uint32_t* r) {
    asm volatile("ldmatrix.sync.aligned.m8n8.x4.shared.b16 {%0,%1,%2,%3}, [%4];"
        : "=r"(r[0]), "=r"(r[1]), "=r"(r[2]), "=r"(r[3]) : "r"(a));
}
__device__ __forceinline__ void mma16816(float* c, const uint32_t* a, const uint32_t* b) {
    asm volatile("mma.sync.aligned.m16n8k16.row.col.f32.bf16.bf16.f32 "
        "{%0,%1,%2,%3}, {%4,%5,%6,%7}, {%8,%9}, {%0,%1,%2,%3};"
        : "+f"(c[0]), "+f"(c[1]), "+f"(c[2]), "+f"(c[3])
        : "r"(a[0]), "r"(a[1]), "r"(a[2]), "r"(a[3]), "r"(b[0]), "r"(b[1]));
}

// stage layout: rows stored with 80-byte stride (odd*16 -> ldmatrix conflict-free)
#define ROWB 80
#define OAH 0
#define OAL 10240
#define OBH 20480
#define OBL 30720
#define STG_ 40960
#define NSTAGE 2
#define QP_DSM (NSTAGE * STG_)

// ---------------- split fp32 -> bf16 hi/lo ----------------
__device__ __forceinline__ void split4(const float* __restrict__ src,
                                       __nv_bfloat16* __restrict__ hi,
                                       __nv_bfloat16* __restrict__ lo, int i) {
    float4 f = reinterpret_cast<const float4*>(src)[i];
    float v[4] = {f.x, f.y, f.z, f.w};
    __nv_bfloat16 h[4], l[4];
#pragma unroll
    for (int j = 0; j < 4; j++) {
        h[j] = __float2bfloat16_rn(v[j]);
        l[j] = __float2bfloat16_rn(v[j] - __bfloat162float(h[j]));
    }
    __nv_bfloat162 a{h[0], h[1]}, b{h[2], h[3]}, c{l[0], l[1]}, d{l[2], l[3]};
    reinterpret_cast<__nv_bfloat162*>(hi)[i*2+0] = a;
    reinterpret_cast<__nv_bfloat162*>(hi)[i*2+1] = b;
    reinterpret_cast<__nv_bfloat162*>(lo)[i*2+0] = c;
    reinterpret_cast<__nv_bfloat162*>(lo)[i*2+1] = d;
}
__global__ void split_q_kernel(const float* __restrict__ s) {
    int i = blockIdx.x * 256 + threadIdx.x;
    if (i < NQ_/4) split4(s, g_ahi, g_alo, i);
}
__global__ void split_w_kernel(const float* __restrict__ s) {
    int i = blockIdx.x * 256 + threadIdx.x;
    if (i < NW_/4) split4(s, g_whi, g_wlo, i);
}

// ---------------- bf16x3 mma.sync GEMM + fused max-pool ----------------
// tile 128(M) x 128(N), 8 warps (2x4), warp tile 64x32, k-chunk 32,
// 2 stages, 2 CTAs/SM. Product-pass ordering: 16 independent MMAs per pass.
__global__ void __launch_bounds__(256, 2) qproj_mma() {
    extern __shared__ char dsm[];
    __shared__ float sred[2][128];

    const uint32_t sb = smem_u32(dsm);
    const int mt = blockIdx.x & 1;
    const int nt = blockIdx.x >> 1;
    const int pair = blockIdx.y;
    const int l = pair % L_;

    const int tid = threadIdx.x;
    const int wid = tid >> 5;
    const int lane = tid & 31;
    const int warp_m = wid >> 2;    // 0..1
    const int warp_n = wid & 3;     // 0..3

    const __nv_bfloat16* Ah = g_ahi + ((size_t)pair * SQ_ + mt * 128) * H_;
    const __nv_bfloat16* Al = g_alo + ((size_t)pair * SQ_ + mt * 128) * H_;
    const __nv_bfloat16* Wh = g_whi + ((size_t)l * R_ + nt * 128) * H_;
    const __nv_bfloat16* Wl = g_wlo + ((size_t)l * R_ + nt * 128) * H_;

    const int r0 = tid >> 2, c0 = tid & 3;
    const int r1 = r0 + 64;

#define REFILL(t)                                                              \
    do {                                                                       \
        const int _k0 = (t) * 32;                                              \
        const uint32_t _s = sb + ((t) & 1) * STG_;                             \
        {                                                                      \
            const uint32_t dd = _s + r0 * ROWB + c0 * 16;                      \
            const size_t off = (size_t)r0 * H_ + _k0 + c0 * 8;                 \
            CP16(dd + OAH, (const void*)(Ah + off));                          \
            CP16(dd + OAL, (const void*)(Al + off));                          \
            CP16(dd + OBH, (const void*)(Wh + off));                          \
            CP16(dd + OBL, (const void*)(Wl + off));                          \
        }                                                                      \
        {                                                                      \
            const uint32_t dd = _s + r1 * ROWB + c0 * 16;                      \
            const size_t off = (size_t)r1 * H_ + _k0 + c0 * 8;                 \
            CP16(dd + OAH, (const void*)(Ah + off));                          \
            CP16(dd + OAL, (const void*)(Al + off));                          \
            CP16(dd + OBH, (const void*)(Wh + off));                          \
            CP16(dd + OBL, (const void*)(Wl + off));                          \
        }                                                                      \
        CP_COMMIT();                                                           \
    } while (0)

    float acc[4][4][4];
#pragma unroll
    for (int m = 0; m < 4; m++)
#pragma unroll
        for (int n = 0; n < 4; n++)
#pragma unroll
            for (int r = 0; r < 4; r++) acc[m][n][r] = 0.0f;

    REFILL(0); REFILL(1);

    const uint32_t aRow = (uint32_t)(warp_m * 64 + (lane & 15)) * ROWB;
    const uint32_t aKsel = ((lane >> 4) & 1) * 16;
    const uint32_t bRow = (uint32_t)(warp_n * 32 + ((lane >> 4) & 1) * 8 + (lane & 7)) * ROWB;
    const uint32_t bKsel = ((lane >> 3) & 1) * 16;

    const int NCH = H_ / 32;   // 80
    for (int t = 0; t < NCH; t++) {
        if (t + 1 < NCH) CP_WAIT1(); else CP_WAIT0();
        __syncthreads();

        const uint32_t s = sb + (t & 1) * STG_;
#pragma unroll
        for (int ks = 0; ks < 2; ks++) {
            const uint32_t ka = ks * 32 + aKsel;
            const uint32_t kb = ks * 32 + bKsel;
            uint32_t a[4][4], b1[2][4], b2[2][4];

            // pass 1: Ah x Bh
#pragma unroll
            for (int m = 0; m < 4; m++)
                ldm_x4(s + OAH + aRow + m * (16 * ROWB) + ka, a[m]);
#pragma unroll
            for (int p = 0; p < 2; p++)
                ldm_x4(s + OBH + bRow + p * (16 * ROWB) + kb, b1[p]);
#pragma unroll
            for (int m = 0; m < 4; m++)
#pragma unroll
                for (int n = 0; n < 4; n++)
                    mma16816(acc[m][n], a[m], &b1[n >> 1][(n & 1) * 2]);

            // pass 2: Ah x Bl
#pragma unroll
            for (int p = 0; p < 2; p++)
                ldm_x4(s + OBL + bRow + p * (16 * ROWB) + kb, b2[p]);
#pragma unroll
            for (int m = 0; m < 4; m++)
#pragma unroll
                for (int n = 0; n < 4; n++)
                    mma16816(acc[m][n], a[m], &b2[n >> 1][(n & 1) * 2]);

            // pass 3: Al x Bh (reuse a[], b1 still live)
#pragma unroll
            for (int m = 0; m < 4; m++)
                ldm_x4(s + OAL + aRow + m * (16 * ROWB) + ka, a[m]);
#pragma unroll
            for (int m = 0; m < 4; m++)
#pragma unroll
                for (int n = 0; n < 4; n++)
                    mma16816(acc[m][n], a[m], &b1[n >> 1][(n & 1) * 2]);
        }
        __syncthreads();
        if (t + 2 < NCH) REFILL(t + 2);
    }

    // epilogue: max over M, fold to sred, then g_qpart
#pragma unroll
    for (int n = 0; n < 4; n++) {
        float m0 = -INFINITY, m1 = -INFINITY;
#pragma unroll
        for (int m = 0; m < 4; m++) {
            m0 = fmaxf(m0, fmaxf(acc[m][n][0], acc[m][n][2]));
            m1 = fmaxf(m1, fmaxf(acc[m][n][1], acc[m][n][3]));
        }
#pragma unroll
        for (int off = 4; off < 32; off <<= 1) {
            m0 = fmaxf(m0, __shfl_xor_sync(0xffffffffu, m0, off));
            m1 = fmaxf(m1, __shfl_xor_sync(0xffffffffu, m1, off));
        }
        if (lane < 4) {
            sred[warp_m][warp_n * 32 + n * 8 + lane * 2 + 0] = m0;
            sred[warp_m][warp_n * 32 + n * 8 + lane * 2 + 1] = m1;
        }
    }
    __syncthreads();
    if (tid < 128) {
        g_qpart[((size_t)pair * 2 + mt) * R_ + nt * 128 + tid] =
            fmaxf(sred[0][tid], sred[1][tid]);
    }
#undef REFILL
}

// ---------------- normalize ----------------
__global__ void qnorm_kernel() {
    const int row = blockIdx.x;
    const int tid = threadIdx.x;
    float v = fmaxf(g_qpart[((size_t)row * 2 + 0) * R_ + tid],
                    g_qpart[((size_t)row * 2 + 1) * R_ + tid]);
    __shared__ float sm[256];
    sm[tid] = v * v;
    __syncthreads();
    for (int s = 128; s > 0; s >>= 1) {
        if (tid < s) sm[tid] += sm[tid + s];
        __syncthreads();
    }
    float inv = 1.0f / fmaxf(sqrtf(sm[0]), 1e-12f);
    g_qvec[(size_t)row * R_ + tid] = v * inv;
}

// ---------------- doc sims ----------------
__global__ void __launch_bounds__(256)
docsim_kernel(const float* __restrict__ doc_keys) {
    const int d = blockIdx.x;
    const int l = blockIdx.y;
    const int tid = threadIdx.x;

    __shared__ float4 qs[B_ * 64];
    for (int i = tid; i < B_ * 64; i += 256) {
        int b = i >> 6, j = i & 63;
        qs[i] = *(const float4*)&g_qvec[((size_t)(b * L_ + l)) * R_ + j * 4];
    }
    __syncthreads();

    const int w = tid >> 5, lane = tid & 31;
    float bmax[16];
#pragma unroll
    for (int b = 0; b < 16; b++) bmax[b] = -INFINITY;

    const float* kb = doc_keys + ((size_t)(d * L_ + l)) * C_ * R_;
    for (int ci = 0; ci < 4; ci++) {
        const int c = w * 4 + ci;
        const float4* kp = (const float4*)(kb + (size_t)c * R_);
        float4 k0 = kp[lane], k1 = kp[lane + 32];
        float n2 = k0.x*k0.x + k0.y*k0.y + k0.z*k0.z + k0.w*k0.w +
                   k1.x*k1.x + k1.y*k1.y + k1.z*k1.z + k1.w*k1.w;
#pragma unroll
        for (int off = 16; off > 0; off >>= 1) n2 += __shfl_xor_sync(0xffffffffu, n2, off);
        const float inv = 1.0f / fmaxf(sqrtf(n2), 1e-12f);
#pragma unroll
        for (int b = 0; b < 16; b++) {
            float4 q0 = qs[b * 64 + lane], q1 = qs[b * 64 + 32 + lane];
            float p = k0.x*q0.x + k0.y*q0.y + k0.z*q0.z + k0.w*q0.w +
                      k1.x*q1.x + k1.y*q1.y + k1.z*q1.z + k1.w*q1.w;
#pragma unroll
            for (int off = 16; off > 0; off >>= 1) p += __shfl_xor_sync(0xffffffffu, p, off);
            bmax[b] = fmaxf(bmax[b], p * inv);
        }
    }
    __shared__ float red[8][16];
    if (lane == 0) {
#pragma unroll
        for (int b = 0; b < 16; b++) red[w][b] = bmax[b];
    }
    __syncthreads();
    if (tid < 16) {
        float m = red[0][tid];
#pragma unroll
        for (int i = 1; i < 8; i++) m = fmaxf(m, red[i][tid]);
        g_sims[((size_t)(tid * D_ + d)) * L_ + l] = m;
    }
}

// ---------------- top-k ----------------
__global__ void topk_kernel(float* __restrict__ out, int out_size) {
    const int b = blockIdx.x;
    const int tid = threadIdx.x;
    __shared__ float sv[D_];
    for (int i = tid; i < D_; i += 256) {
        const float* p = &g_sims[((size_t)(b * D_ + i)) * L_];
        float ssum = 0.0f;
#pragma unroll
        for (int l = 0; l < L_; l++) ssum += p[l];
        sv[i] = ssum / (float)L_;
    }
    __syncthreads();
    __shared__ float rv[256];
    __shared__ int ri[256];
    for (int k = 0; k < TOPK_; k++) {
        float best = -INFINITY; int bi = 0x7fffffff;
        for (int i = tid; i < D_; i += 256) {
            float v = sv[i];
            if (v > best || (v == best && i < bi)) { best = v; bi = i; }
        }
        rv[tid] = best; ri[tid] = bi;
        __syncthreads();
        for (int s = 128; s > 0; s >>= 1) {
            if (tid < s) {
                float v2 = rv[tid + s]; int i2 = ri[tid + s];
                if (v2 > rv[tid] || (v2 == rv[tid] && i2 < ri[tid])) { rv[tid] = v2; ri[tid] = i2; }
            }
            __syncthreads();
        }
        if (tid == 0) {
            out[b * TOPK_ + k] = rv[0];
            if (out_size >= 2 * B_ * TOPK_) out[B_ * TOPK_ + b * TOPK_ + k] = (float)ri[0];
            sv[ri[0]] = -INFINITY;
        }
        __syncthreads();
    }
}

// ---------------------------------------------------------------------------
extern "C" void kernel_launch(void* const* d_in, const int* in_sizes, int n_in,
                              void* d_out, int out_size) {
    const float* q_hs     = (const float*)d_in[0];
    const float* w_q      = (const float*)d_in[1];
    const float* doc_keys = (const float*)d_in[2];
    (void)in_sizes; (void)n_in;

    cudaFuncSetAttribute(qproj_mma, cudaFuncAttributeMaxDynamicSharedMemorySize, QP_DSM);

    split_q_kernel<<<NQ_ / 4 / 256, 256>>>(q_hs);
    split_w_kernel<<<NW_ / 4 / 256, 256>>>(w_q);
    dim3 gA(4, B_ * L_);
    qproj_mma<<<gA, 256, QP_DSM>>>();
    qnorm_kernel<<<B_ * L_, 256>>>();
    dim3 gB(D_, L_);
    docsim_kernel<<<gB, 256>>>(doc_keys);
    topk_kernel<<<B_, 256>>>((float*)d_out, out_size);
}

// round 8
// speedup vs baseline: 2.7244x; 1.1017x over previous
#include <cuda_runtime.h>
#include <cuda_bf16.h>
#include <math.h>
#include <stdint.h>

#define B_   16
#define L_   18
#define SQ_  256
#define H_   2560
#define R_   256
#define D_   2048
#define C_   32
#define TOPK_ 16

#define NCHK 80          // H / 32
#define TILE_BYTES 16384 // hi 8KB + lo 8KB, 128 rows x 64B

__device__ float g_qpart[2 * B_ * L_ * R_];
__device__ float g_qvec[B_ * L_ * R_];
__device__ float g_sims[B_ * D_ * L_];
// packed chunk tiles: [tile][chunk][ hi 128x64B (xor-swizzled) | lo 8KB ]
__device__ __align__(16) uint8_t g_apack[B_ * L_ * 2 * NCHK * TILE_BYTES]; // 755MB
__device__ __align__(16) uint8_t g_wpack[L_ * 2 * NCHK * TILE_BYTES];      // 47MB

// ---------------- helpers ----------------
__device__ __forceinline__ uint32_t smem_u32(const void* p) {
    uint32_t a;
    asm("{ .reg .u64 t; cvta.to.shared.u64 t, %1; cvt.u32.u64 %0, t; }" : "=r"(a) : "l"(p));
    return a;
}
#define MBAR_INIT(a, c) asm volatile("mbarrier.init.shared.b64 [%0], %1;" :: "r"(a), "r"(c) : "memory")
#define MBAR_EXPECT_TX(a, n) asm volatile("mbarrier.arrive.expect_tx.shared.b64 _, [%0], %1;" :: "r"(a), "r"(n) : "memory")
#define MBAR_WAIT(a, par) do {                                                  \
    uint32_t _m=(a), _p=(par), _d;                                              \
    asm volatile("{\n\t.reg .pred p;\n\t"                                       \
      "mbarrier.try_wait.parity.acquire.cta.shared::cta.b64 p, [%1], %2;\n\t"   \
      "selp.b32 %0,1,0,p;\n\t}" : "=r"(_d) : "r"(_m), "r"(_p) : "memory");      \
    if (!_d) { asm volatile("{\n\t.reg .pred P1;\n\tW_%=:\n\t"                  \
      "mbarrier.try_wait.parity.acquire.cta.shared::cta.b64 P1, [%0], %1, 0x989680;\n\t" \
      "@P1 bra.uni WD_%=;\n\tbra.uni W_%=;\n\tWD_%=:\n\t}" :: "r"(_m), "r"(_p) : "memory"); } \
} while (0)
#define BULK_LD(dst, src, sz, mb) \
    asm volatile("cp.async.bulk.shared::cluster.global.mbarrier::complete_tx::bytes [%0], [%1], %2, [%3];" \
                 :: "r"(dst), "l"(src), "r"(sz), "r"(mb) : "memory")

__device__ __forceinline__ void ldm_x4(uint32_t a, uint32_t* r) {
    asm volatile("ldmatrix.sync.aligned.m8n8.x4.shared.b16 {%0,%1,%2,%3}, [%4];"
        : "=r"(r[0]), "=r"(r[1]), "=r"(r[2]), "=r"(r[3]) : "r"(a));
}
__device__ __forceinline__ void mma16816(float* c, const uint32_t* a, const uint32_t* b) {
    asm volatile("mma.sync.aligned.m16n8k16.row.col.f32.bf16.bf16.f32 "
        "{%0,%1,%2,%3}, {%4,%5,%6,%7}, {%8,%9}, {%0,%1,%2,%3};"
        : "+f"(c[0]), "+f"(c[1]), "+f"(c[2]), "+f"(c[3])
        : "r"(a[0]), "r"(a[1]), "r"(a[2]), "r"(a[3]), "r"(b[0]), "r"(b[1]));
}

#define STG_ 32768
#define NSTAGE 3
#define QP_DSM (NSTAGE * STG_)

// ---------------- pack kernels: fp32 -> bf16 hi/lo chunk tiles ----------------
// tile layout: 128 rows x 64B; row r chunk c (16B) stored at r*64 + ((c ^ ((r>>1)&3))<<4)
__device__ __forceinline__ void split8(const float* __restrict__ p, uint4& hi, uint4& lo) {
    float4 f0 = *(const float4*)p;
    float4 f1 = *(const float4*)(p + 4);
    float v[8] = {f0.x, f0.y, f0.z, f0.w, f1.x, f1.y, f1.z, f1.w};
    uint32_t hw[4], lw[4];
#pragma unroll
    for (int j = 0; j < 4; j++) {
        __nv_bfloat16 h0 = __float2bfloat16_rn(v[2*j]);
        __nv_bfloat16 h1 = __float2bfloat16_rn(v[2*j+1]);
        __nv_bfloat16 l0 = __float2bfloat16_rn(v[2*j]   - __bfloat162float(h0));
        __nv_bfloat16 l1 = __float2bfloat16_rn(v[2*j+1] - __bfloat162float(h1));
        __nv_bfloat162 hp{h0, h1}, lp{l0, l1};
        hw[j] = *(uint32_t*)&hp;
        lw[j] = *(uint32_t*)&lp;
    }
    hi = make_uint4(hw[0], hw[1], hw[2], hw[3]);
    lo = make_uint4(lw[0], lw[1], lw[2], lw[3]);
}

// grid.x = ntiles*NCHK; src row stride H_; 256 threads: row=tid>>1, half=tid&1
__device__ __forceinline__ void pack_tile(const float* __restrict__ srcbase,
                                          uint8_t* __restrict__ dstbase,
                                          int chunk, int tid) {
    const int row = tid >> 1;
    const int half = tid & 1;
    const uint32_t X = (row >> 1) & 3;
    const float* src = srcbase + (size_t)row * H_ + chunk * 32;
#pragma unroll
    for (int j = 0; j < 2; j++) {
        const int c = half * 2 + j;
        uint4 hi, lo;
        split8(src + c * 8, hi, lo);
        const uint32_t off = row * 64 + ((c ^ X) << 4);
        *(uint4*)(dstbase + off) = hi;
        *(uint4*)(dstbase + 8192 + off) = lo;
    }
}

__global__ void pack_a_kernel(const float* __restrict__ q_hs) {
    const int x = blockIdx.x;               // tileIdx*NCHK + chunk
    const int chunk = x % NCHK;
    const int tile = x / NCHK;              // pair*2 + mt
    const int mt = tile & 1;
    const int pair = tile >> 1;
    const float* src = q_hs + ((size_t)(pair * SQ_ + mt * 128)) * H_;
    pack_tile(src, g_apack + (size_t)x * TILE_BYTES, chunk, threadIdx.x);
}
__global__ void pack_w_kernel(const float* __restrict__ w_q) {
    const int x = blockIdx.x;               // (l*2+nt)*NCHK + chunk
    const int chunk = x % NCHK;
    const int tile = x / NCHK;              // l*2 + nt
    const int nt = tile & 1;
    const int l = tile >> 1;
    const float* src = w_q + ((size_t)(l * R_ + nt * 128)) * H_;
    pack_tile(src, g_wpack + (size_t)x * TILE_BYTES, chunk, threadIdx.x);
}

// ---------------- bf16x3 mma.sync GEMM, bulk-TMA fed, fused max-pool --------
// tile 128(M) x 128(N), 8 warps (2x4), warp tile 64x32, k-chunk 32,
// 3-stage bulk-copy ring, 2 CTAs/SM.
__global__ void __launch_bounds__(256, 2) qproj_mma() {
    extern __shared__ char dsm[];
    __shared__ float sred[2][128];
    __shared__ uint64_t mbars[NSTAGE];

    const uint32_t sb = smem_u32(dsm);
    const int mt = blockIdx.x & 1;
    const int nt = blockIdx.x >> 1;
    const int pair = blockIdx.y;
    const int l = pair % L_;

    const int tid = threadIdx.x;
    const int wid = tid >> 5;
    const int lane = tid & 31;
    const int warp_m = wid >> 2;
    const int warp_n = wid & 3;

    const uint8_t* Asrc = g_apack + (size_t)((pair * 2 + mt) * NCHK) * TILE_BYTES;
    const uint8_t* Bsrc = g_wpack + (size_t)((l * 2 + nt) * NCHK) * TILE_BYTES;

    const uint32_t mb0 = smem_u32(&mbars[0]);
    if (tid == 0) {
#pragma unroll
        for (int i = 0; i < NSTAGE; i++) MBAR_INIT(mb0 + i * 8, 1);
    }
    __syncthreads();

#define REFILL(t, s)                                                           \
    do {                                                                       \
        if (tid == 0) {                                                        \
            const uint32_t _mb = mb0 + (s) * 8;                                \
            MBAR_EXPECT_TX(_mb, 2 * TILE_BYTES);                               \
            BULK_LD(sb + (s) * STG_,         Asrc + (size_t)(t) * TILE_BYTES,  \
                    TILE_BYTES, _mb);                                          \
            BULK_LD(sb + (s) * STG_ + 16384, Bsrc + (size_t)(t) * TILE_BYTES,  \
                    TILE_BYTES, _mb);                                          \
        }                                                                      \
    } while (0)

    REFILL(0, 0); REFILL(1, 1); REFILL(2, 2);

    float acc[4][4][4];
#pragma unroll
    for (int m = 0; m < 4; m++)
#pragma unroll
        for (int n = 0; n < 4; n++)
#pragma unroll
            for (int r = 0; r < 4; r++) acc[m][n][r] = 0.0f;

    // per-lane constants for xor-swizzled ldmatrix addressing (64B rows)
    const uint32_t XA = ((lane & 15) >> 1) & 3;
    const uint32_t rowA = (uint32_t)(warp_m * 64 + (lane & 15)) * 64;
    const uint32_t cAsel = (lane >> 4) & 1;
    const uint32_t XB = ((lane & 7) >> 1) & 3;
    const uint32_t rowB = (uint32_t)(warp_n * 32 + ((lane >> 4) & 1) * 8 + (lane & 7)) * 64;
    const uint32_t cBsel = (lane >> 3) & 1;

    int s = 0, ph = 0;
    for (int t = 0; t < NCHK; t++) {
        MBAR_WAIT(mb0 + s * 8, ph);
        const uint32_t stg = sb + s * STG_;
#pragma unroll
        for (int ks = 0; ks < 2; ks++) {
            const uint32_t colA = (((ks * 2 + cAsel) ^ XA) << 4);
            const uint32_t colB = (((ks * 2 + cBsel) ^ XB) << 4);
            const uint32_t aBase = stg + rowA + colA;           // hi; lo at +8192
            const uint32_t bBase = stg + 16384 + rowB + colB;   // hi; lo at +8192
            uint32_t a[4][4], b1[2][4], b2[2][4];

            // pass 1: Ah x Bh
#pragma unroll
            for (int m = 0; m < 4; m++) ldm_x4(aBase + m * 1024, a[m]);
#pragma unroll
            for (int p = 0; p < 2; p++) ldm_x4(bBase + p * 1024, b1[p]);
#pragma unroll
            for (int m = 0; m < 4; m++)
#pragma unroll
                for (int n = 0; n < 4; n++)
                    mma16816(acc[m][n], a[m], &b1[n >> 1][(n & 1) * 2]);

            // pass 2: Ah x Bl
#pragma unroll
            for (int p = 0; p < 2; p++) ldm_x4(bBase + 8192 + p * 1024, b2[p]);
#pragma unroll
            for (int m = 0; m < 4; m++)
#pragma unroll
                for (int n = 0; n < 4; n++)
                    mma16816(acc[m][n], a[m], &b2[n >> 1][(n & 1) * 2]);

            // pass 3: Al x Bh
#pragma unroll
            for (int m = 0; m < 4; m++) ldm_x4(aBase + 8192 + m * 1024, a[m]);
#pragma unroll
            for (int m = 0; m < 4; m++)
#pragma unroll
                for (int n = 0; n < 4; n++)
                    mma16816(acc[m][n], a[m], &b1[n >> 1][(n & 1) * 2]);
        }
        __syncthreads();
        if (t + NSTAGE < NCHK) REFILL(t + NSTAGE, s);
        if (++s == NSTAGE) { s = 0; ph ^= 1; }
    }

    // epilogue: max over M, fold to sred, then g_qpart
#pragma unroll
    for (int n = 0; n < 4; n++) {
        float m0 = -INFINITY, m1 = -INFINITY;
#pragma unroll
        for (int m = 0; m < 4; m++) {
            m0 = fmaxf(m0, fmaxf(acc[m][n][0], acc[m][n][2]));
            m1 = fmaxf(m1, fmaxf(acc[m][n][1], acc[m][n][3]));
        }
#pragma unroll
        for (int off = 4; off < 32; off <<= 1) {
            m0 = fmaxf(m0, __shfl_xor_sync(0xffffffffu, m0, off));
            m1 = fmaxf(m1, __shfl_xor_sync(0xffffffffu, m1, off));
        }
        if (lane < 4) {
            sred[warp_m][warp_n * 32 + n * 8 + lane * 2 + 0] = m0;
            sred[warp_m][warp_n * 32 + n * 8 + lane * 2 + 1] = m1;
        }
    }
    __syncthreads();
    if (tid < 128) {
        g_qpart[((size_t)pair * 2 + mt) * R_ + nt * 128 + tid] =
            fmaxf(sred[0][tid], sred[1][tid]);
    }
#undef REFILL
}

// ---------------- normalize ----------------
__global__ void qnorm_kernel() {
    const int row = blockIdx.x;
    const int tid = threadIdx.x;
    float v = fmaxf(g_qpart[((size_t)row * 2 + 0) * R_ + tid],
                    g_qpart[((size_t)row * 2 + 1) * R_ + tid]);
    __shared__ float sm[256];
    sm[tid] = v * v;
    __syncthreads();
    for (int s = 128; s > 0; s >>= 1) {
        if (tid < s) sm[tid] += sm[tid + s];
        __syncthreads();
    }
    float inv = 1.0f / fmaxf(sqrtf(sm[0]), 1e-12f);
    g_qvec[(size_t)row * R_ + tid] = v * inv;
}

// ---------------- doc sims ----------------
__global__ void __launch_bounds__(256)
docsim_kernel(const float* __restrict__ doc_keys) {
    const int d = blockIdx.x;
    const int l = blockIdx.y;
    const int tid = threadIdx.x;

    __shared__ float4 qs[B_ * 64];
    for (int i = tid; i < B_ * 64; i += 256) {
        int b = i >> 6, j = i & 63;
        qs[i] = *(const float4*)&g_qvec[((size_t)(b * L_ + l)) * R_ + j * 4];
    }
    __syncthreads();

    const int w = tid >> 5, lane = tid & 31;
    float bmax[16];
#pragma unroll
    for (int b = 0; b < 16; b++) bmax[b] = -INFINITY;

    const float* kb = doc_keys + ((size_t)(d * L_ + l)) * C_ * R_;
    for (int ci = 0; ci < 4; ci++) {
        const int c = w * 4 + ci;
        const float4* kp = (const float4*)(kb + (size_t)c * R_);
        float4 k0 = kp[lane], k1 = kp[lane + 32];
        float n2 = k0.x*k0.x + k0.y*k0.y + k0.z*k0.z + k0.w*k0.w +
                   k1.x*k1.x + k1.y*k1.y + k1.z*k1.z + k1.w*k1.w;
#pragma unroll
        for (int off = 16; off > 0; off >>= 1) n2 += __shfl_xor_sync(0xffffffffu, n2, off);
        const float inv = 1.0f / fmaxf(sqrtf(n2), 1e-12f);
#pragma unroll
        for (int b = 0; b < 16; b++) {
            float4 q0 = qs[b * 64 + lane], q1 = qs[b * 64 + 32 + lane];
            float p = k0.x*q0.x + k0.y*q0.y + k0.z*q0.z + k0.w*q0.w +
                      k1.x*q1.x + k1.y*q1.y + k1.z*q1.z + k1.w*q1.w;
#pragma unroll
            for (int off = 16; off > 0; off >>= 1) p += __shfl_xor_sync(0xffffffffu, p, off);
            bmax[b] = fmaxf(bmax[b], p * inv);
        }
    }
    __shared__ float red[8][16];
    if (lane == 0) {
#pragma unroll
        for (int b = 0; b < 16; b++) red[w][b] = bmax[b];
    }
    __syncthreads();
    if (tid < 16) {
        float m = red[0][tid];
#pragma unroll
        for (int i = 1; i < 8; i++) m = fmaxf(m, red[i][tid]);
        g_sims[((size_t)(tid * D_ + d)) * L_ + l] = m;
    }
}

// ---------------- top-k ----------------
__global__ void topk_kernel(float* __restrict__ out, int out_size) {
    const int b = blockIdx.x;
    const int tid = threadIdx.x;
    __shared__ float sv[D_];
    for (int i = tid; i < D_; i += 256) {
        const float* p = &g_sims[((size_t)(b * D_ + i)) * L_];
        float ssum = 0.0f;
#pragma unroll
        for (int l = 0; l < L_; l++) ssum += p[l];
        sv[i] = ssum / (float)L_;
    }
    __syncthreads();
    __shared__ float rv[256];
    __shared__ int ri[256];
    for (int k = 0; k < TOPK_; k++) {
        float best = -INFINITY; int bi = 0x7fffffff;
        for (int i = tid; i < D_; i += 256) {
            float v = sv[i];
            if (v > best || (v == best && i < bi)) { best = v; bi = i; }
        }
        rv[tid] = best; ri[tid] = bi;
        __syncthreads();
        for (int s = 128; s > 0; s >>= 1) {
            if (tid < s) {
                float v2 = rv[tid + s]; int i2 = ri[tid + s];
                if (v2 > rv[tid] || (v2 == rv[tid] && i2 < ri[tid])) { rv[tid] = v2; ri[tid] = i2; }
            }
            __syncthreads();
        }
        if (tid == 0) {
            out[b * TOPK_ + k] = rv[0];
            if (out_size >= 2 * B_ * TOPK_) out[B_ * TOPK_ + b * TOPK_ + k] = (float)ri[0];
            sv[ri[0]] = -INFINITY;
        }
        __syncthreads();
    }
}

// ---------------------------------------------------------------------------
extern "C" void kernel_launch(void* const* d_in, const int* in_sizes, int n_in,
                              void* d_out, int out_size) {
    const float* q_hs     = (const float*)d_in[0];
    const float* w_q      = (const float*)d_in[1];
    const float* doc_keys = (const float*)d_in[2];
    (void)in_sizes; (void)n_in;

    cudaFuncSetAttribute(qproj_mma, cudaFuncAttributeMaxDynamicSharedMemorySize, QP_DSM);

    pack_a_kernel<<<B_ * L_ * 2 * NCHK, 256>>>(q_hs);
    pack_w_kernel<<<L_ * 2 * NCHK, 256>>>(w_q);
    dim3 gA(4, B_ * L_);
    qproj_mma<<<gA, 256, QP_DSM>>>();
    qnorm_kernel<<<B_ * L_, 256>>>();
    dim3 gB(D_, L_);
    docsim_kernel<<<gB, 256>>>(doc_keys);
    topk_kernel<<<B_, 256>>>((float*)d_out, out_size);
}